// round 15
// baseline (speedup 1.0000x reference)
#include <cuda_runtime.h>
#include <cuda_fp16.h>
#include <math.h>
#include <cstdint>

#define N_PTS 16384
#define D 16
// t1 = -0.5*D*log(2*pi) - log(0.1)
#define T1_CONST (-12.400431438280716f)
#define LOG_EPS  (-18.420680743952367f)   // logf(1e-8)
#define FLAG_THRESH (-45.0f)

#define ROWB 32                 // dense f16 row bytes in gmem (16 halves, K=16 exactly)
#define SROWB 48                // smem row stride: 16B-aligned, conflict-free ldmatrix
#define BT 128                  // base rows per smem tile
#define NSTAGE 3
#define NSPLITS 8
#define MB_ROWS 256             // eval rows per CTA (8 warps x m32)
#define TILES_PER_SPLIT ((N_PTS / NSPLITS) / BT)   // 16

// Scratch (no device allocation allowed)
__device__ unsigned char g_A[N_PTS * ROWB];     // eval rows: f16(100*e)
__device__ unsigned char g_B[N_PTS * ROWB];     // base rows: f16(b)
__device__ float  g_ce[N_PTS];                  // t1 - 50||e||^2   (fp32 exact)
__device__ __half g_cbh[N_PTS];                 // -50||b||^2       (f16, screen only)
__device__ float  g_rowmax[NSPLITS][N_PTS];     // max_j (dot + cb), per split (ce added later)

__device__ __forceinline__ uint32_t smem_u32(const void* p) {
    uint32_t a;
    asm("{ .reg .u64 t; cvta.to.shared.u64 t, %1; cvt.u32.u64 %0, t; }" : "=r"(a) : "l"(p));
    return a;
}

#define LDMX4(r0, r1, r2, r3, a) \
    asm volatile("ldmatrix.sync.aligned.m8n8.x4.shared.b16 {%0,%1,%2,%3}, [%4];" \
        : "=r"(r0), "=r"(r1), "=r"(r2), "=r"(r3) : "r"(a))

// f16-accumulate HMMA: D,C are 2 packed regs ({row r, cols c,c+1}, {row r+8, same cols})
#define MMA16816H(d0,d1, a0,a1,a2,a3, b0,b1, c0,c1) \
    asm volatile("mma.sync.aligned.m16n8k16.row.col.f16.f16.f16.f16 " \
        "{%0,%1},{%2,%3,%4,%5},{%6,%7},{%8,%9};" \
        : "=r"(d0), "=r"(d1) \
        : "r"(a0), "r"(a1), "r"(a2), "r"(a3), "r"(b0), "r"(b1), "r"(c0), "r"(c1))

#define HMAX2(d, a, b) \
    asm("max.f16x2 %0, %1, %2;" : "=r"(d) : "r"(a), "r"(b))

__device__ __forceinline__ void cp16(uint32_t dst, const void* src) {
    asm volatile("cp.async.cg.shared.global [%0], [%1], 16;" :: "r"(dst), "l"(src));
}
#define CP_COMMIT() asm volatile("cp.async.commit_group;" ::: "memory")
#define CP_WAIT(n)  asm volatile("cp.async.wait_group %0;" :: "n"(n) : "memory")

// ---------------- prep: 4 threads per row (quad shfl-reduce), latency-optimized ----
__global__ void kde_prep(const float* __restrict__ xe, const float* __restrict__ xb) {
    int gt = blockIdx.x * blockDim.x + threadIdx.x;      // 0..131071
    int g = gt >> 2;                                     // row id 0..32767
    int q = gt & 3;                                      // quarter within row
    bool is_e = g < N_PTS;
    int row = is_e ? g : g - N_PTS;
    const float* src = (is_e ? xe : xb) + (size_t)row * D;

    float4 t = ((const float4*)src)[q];
    float n2 = t.x*t.x + t.y*t.y + t.z*t.z + t.w*t.w;
    n2 += __shfl_xor_sync(0xffffffffu, n2, 1);
    n2 += __shfl_xor_sync(0xffffffffu, n2, 2);           // full ||x||^2 in all 4 lanes

    float sc = is_e ? 100.f : 1.f;
    __half r[4];
    r[0] = __float2half(sc * t.x);
    r[1] = __float2half(sc * t.y);
    r[2] = __float2half(sc * t.z);
    r[3] = __float2half(sc * t.w);

    if (q == 0) {
        if (is_e) g_ce[row] = T1_CONST - 50.f * n2;
        else      g_cbh[row] = __float2half(-50.f * n2);
    }
    uint2* dst = (uint2*)((is_e ? g_A : g_B) + (size_t)row * ROWB + q * 8);
    *dst = *(const uint2*)r;
}

// ---------------- main: f16 HMMA GEMM, cb in packed c-operand, HMAX2 epilogue ------
// grid = 512: blockIdx.x = mblk*8 + split. CTA = 256 thr (8 warps), warp owns m32,
// CTA covers m256. 3-stage cp.async ring, ONE __syncthreads per tile.
__global__ void __launch_bounds__(256) kde_main() {
    __shared__ __align__(16) unsigned char sA[MB_ROWS * SROWB];
    __shared__ __align__(16) unsigned char sB[NSTAGE][BT * SROWB];
    __shared__ __align__(16) __half scb[NSTAGE][BT];

    const int tid = threadIdx.x, w = tid >> 5, lane = tid & 31;
    const int mblk = blockIdx.x >> 3, split = blockIdx.x & 7;

    const unsigned char* Ag = g_A + (size_t)mblk * MB_ROWS * ROWB;
    const unsigned char* Bg = g_B + (size_t)split * (N_PTS / NSPLITS) * ROWB;
    const __half* cbg = g_cbh + (size_t)split * (N_PTS / NSPLITS);

    const uint32_t sA_a = smem_u32(sA);
    uint32_t sB_a[NSTAGE], scb_a[NSTAGE];
    #pragma unroll
    for (int s = 0; s < NSTAGE; s++) { sB_a[s] = smem_u32(sB[s]); scb_a[s] = smem_u32(scb[s]); }

    // copy helper: B tile -> stage buffer (32B rows -> 48B smem stride), 1 cp16/thread
    auto issue_tile = [&](int t, int s) {
        const unsigned char* src = Bg + (size_t)t * BT * ROWB;
        int i = tid;                          // 256 chunks of 16B
        uint32_t row = i >> 1, c = i & 1;
        cp16(sB_a[s] + row * SROWB + c * 16, src + (size_t)i * 16);
        if (tid < 16) cp16(scb_a[s] + tid * 16, cbg + (size_t)t * BT + tid * 8);
    };

    // Prologue: group0 = A + tile0, group1 = tile1.
    {
        #pragma unroll
        for (int k = 0; k < 2; k++) {
            int i = tid + k * 256;            // 512 chunks of 16B (256 rows)
            uint32_t row = i >> 1, c = i & 1;
            cp16(sA_a + row * SROWB + c * 16, Ag + (size_t)i * 16);
        }
        issue_tile(0, 0);
        CP_COMMIT();
        issue_tile(1, 1);
        CP_COMMIT();
        CP_WAIT(1);              // group0 (A + tile0) complete
    }
    __syncthreads();

    // A fragments (2 m16-tiles, K=16), loaded once per warp.
    uint32_t af[2][4];
    {
        int grp = lane >> 3;
        int arow = ((grp & 1) << 3) + (lane & 7);      // 0..15 within m16 tile
        int akb  = (grp >> 1) << 4;                    // 0 or 16 bytes
        #pragma unroll
        for (int mt = 0; mt < 2; mt++) {
            uint32_t addr = sA_a + (uint32_t)(w * 32 + mt * 16 + arow) * SROWB + (uint32_t)akb;
            LDMX4(af[mt][0], af[mt][1], af[mt][2], af[mt][3], addr);
        }
    }

    // B ldmatrix: one x4 covers 16 cols x K16 ({b0,b1}=cols 0-7, {b2,b3}=cols 8-15).
    const uint32_t boff = ((uint32_t)(((lane >> 4) << 3) + (lane & 7))) * SROWB
                        + (uint32_t)(((lane >> 3) & 1) << 4);
    const uint32_t cb_off = (uint32_t)((lane & 3) << 2);   // byte offset of packed half2 (cols 2q,2q+1)
    const uint32_t NEG_INF2 = 0xFC00FC00u;                 // (-inf, -inf) f16x2
    uint32_t rm[4] = {NEG_INF2, NEG_INF2, NEG_INF2, NEG_INF2};

    for (int t = 0; t < TILES_PER_SPLIT; t++) {
        const int cur = t % NSTAGE;

        if (t + 1 < TILES_PER_SPLIT) { CP_WAIT(1); } else { CP_WAIT(0); }
        __syncthreads();   // tile t ready everywhere; buf (t+2)%3 free (all done with t-1)

        const uint32_t bbase = sB_a[cur] + boff;
        const uint32_t cbase = scb_a[cur] + cb_off;
        #pragma unroll
        for (int n16 = 0; n16 < 8; n16++) {
            uint32_t b0, b1, b2, b3;
            LDMX4(b0, b1, b2, b3, bbase + (uint32_t)n16 * (16 * SROWB));
            uint32_t cA, cB;     // packed (cb_c, cb_c+1) for this thread's col pair
            asm volatile("ld.shared.b32 %0, [%1];" : "=r"(cA) : "r"(cbase + n16 * 32));
            asm volatile("ld.shared.b32 %0, [%1];" : "=r"(cB) : "r"(cbase + n16 * 32 + 16));
            #pragma unroll
            for (int mt = 0; mt < 2; mt++) {
                uint32_t d0, d1, e0, e1;
                MMA16816H(d0, d1, af[mt][0], af[mt][1], af[mt][2], af[mt][3], b0, b1, cA, cA);
                MMA16816H(e0, e1, af[mt][0], af[mt][1], af[mt][2], af[mt][3], b2, b3, cB, cB);
                uint32_t t0, t1;
                HMAX2(t0, d0, e0);                    // row r
                HMAX2(rm[mt * 2 + 0], rm[mt * 2 + 0], t0);
                HMAX2(t1, d1, e1);                    // row r+8
                HMAX2(rm[mt * 2 + 1], rm[mt * 2 + 1], t1);
            }
        }

        if (t + 2 < TILES_PER_SPLIT) {
            issue_tile(t + 2, (t + 2) % NSTAGE);
            CP_COMMIT();
        }
    }

    // reduce across the 4-lane quad (cols), then unpack and store per-row maxes
    #pragma unroll
    for (int i = 0; i < 4; i++) {
        uint32_t o;
        o = __shfl_xor_sync(0xffffffffu, rm[i], 1); HMAX2(rm[i], rm[i], o);
        o = __shfl_xor_sync(0xffffffffu, rm[i], 2); HMAX2(rm[i], rm[i], o);
    }
    if ((lane & 3) == 0) {
        int q = lane >> 2;
        int base = mblk * MB_ROWS + w * 32;
        #pragma unroll
        for (int i = 0; i < 4; i++) {
            __half2 h = *(__half2*)&rm[i];
            float m = fmaxf(__half2float(__low2half(h)), __half2float(__high2half(h)));
            int roff = (i & 1) * 8 + (i >> 1) * 16;      // rm: {mt0 r, mt0 r+8, mt1 r+16, mt1 r+24}
            g_rowmax[split][base + q + roff] = m;
        }
    }
}

// ---------------- final: exact recompute for flagged rows, const for the rest ----
__global__ void kde_final(const float* __restrict__ xe, const float* __restrict__ xb,
                          float* __restrict__ out) {
    __shared__ int s_list[128];
    __shared__ int s_cnt;
    __shared__ float s_red[128];
    __shared__ float s_e[D];

    int tid = threadIdx.x;
    int row = blockIdx.x * 128 + tid;
    if (tid == 0) s_cnt = 0;
    __syncthreads();

    float mv = -3.0e38f;
    #pragma unroll
    for (int k = 0; k < NSPLITS; k++) mv = fmaxf(mv, g_rowmax[k][row]);
    mv += g_ce[row];
    if (mv > FLAG_THRESH) {
        int p = atomicAdd(&s_cnt, 1);
        s_list[p] = row;
    } else {
        out[row] = LOG_EPS;
    }
    __syncthreads();

    for (int f = 0; f < s_cnt; f++) {
        int i = s_list[f];
        if (tid < D) s_e[tid] = xe[(size_t)i * D + tid];
        __syncthreads();
        float e[D];
        #pragma unroll
        for (int k = 0; k < D; k++) e[k] = s_e[k];
        float acc = 0.f;
        for (int j = tid; j < N_PTS; j += 128) {
            const float4* bp = (const float4*)(xb + (size_t)j * D);
            float sq = 0.f;
            #pragma unroll
            for (int q = 0; q < 4; q++) {
                float4 b = bp[q];
                float d0 = e[4*q+0] - b.x, d1 = e[4*q+1] - b.y;
                float d2 = e[4*q+2] - b.z, d3 = e[4*q+3] - b.w;
                sq += d0*d0 + d1*d1 + d2*d2 + d3*d3;
            }
            float s = T1_CONST - 50.f * sq;
            if (s > -87.0f) acc += __expf(s);
        }
        s_red[tid] = acc;
        __syncthreads();
        for (int st = 64; st > 0; st >>= 1) {
            if (tid < st) s_red[tid] += s_red[tid + st];
            __syncthreads();
        }
        if (tid == 0) out[i] = logf(1e-8f + s_red[0] * (1.0f / (float)N_PTS));
        __syncthreads();
    }
}

extern "C" void kernel_launch(void* const* d_in, const int* in_sizes, int n_in,
                              void* d_out, int out_size) {
    const float* x_eval = (const float*)d_in[0];
    const float* x_base = (const float*)d_in[1];
    float* out = (float*)d_out;

    kde_prep<<<(2 * N_PTS * 4) / 256, 256>>>(x_eval, x_base);
    kde_main<<<(N_PTS / MB_ROWS) * NSPLITS, 256>>>();
    kde_final<<<N_PTS / 128, 128>>>(x_eval, x_base, out);
}

// round 16
// speedup vs baseline: 1.1382x; 1.1382x over previous
#include <cuda_runtime.h>
#include <cuda_fp16.h>
#include <math.h>
#include <cstdint>

#define N_PTS 16384
#define D 16
// t1 = -0.5*D*log(2*pi) - log(0.1)
#define T1_CONST (-12.400431438280716f)
#define LOG_EPS  (-18.420680743952367f)   // logf(1e-8)
#define FLAG_THRESH (-45.0f)

#define ROWB 32                 // dense f16 row bytes in gmem (16 halves, K=16 exactly)
#define SROWB 48                // smem row stride: 16B-aligned, conflict-free ldmatrix
#define BT 128                  // base rows per smem tile
#define NSTAGE 3
#define NSPLITS 16
#define MB_ROWS 256             // eval rows per CTA (4 warps x m64)
#define TILES_PER_SPLIT ((N_PTS / NSPLITS) / BT)   // 8

// Scratch (no device allocation allowed)
__device__ unsigned char g_A[N_PTS * ROWB];     // eval rows: f16(100*e)
__device__ unsigned char g_B[N_PTS * ROWB];     // base rows: f16(b)
__device__ float  g_ce[N_PTS];                  // t1 - 50||e||^2   (fp32 exact)
__device__ __half g_cbh[N_PTS];                 // -50||b||^2       (f16, screen only)
__device__ float  g_rowmax[NSPLITS][N_PTS];     // max_j (dot + cb), per split (ce added later)

__device__ __forceinline__ uint32_t smem_u32(const void* p) {
    uint32_t a;
    asm("{ .reg .u64 t; cvta.to.shared.u64 t, %1; cvt.u32.u64 %0, t; }" : "=r"(a) : "l"(p));
    return a;
}

#define LDMX4(r0, r1, r2, r3, a) \
    asm volatile("ldmatrix.sync.aligned.m8n8.x4.shared.b16 {%0,%1,%2,%3}, [%4];" \
        : "=r"(r0), "=r"(r1), "=r"(r2), "=r"(r3) : "r"(a))

// f16-accumulate HMMA: D,C are 2 packed regs ({row r, cols c,c+1}, {row r+8, same cols})
#define MMA16816H(d0,d1, a0,a1,a2,a3, b0,b1, c0,c1) \
    asm volatile("mma.sync.aligned.m16n8k16.row.col.f16.f16.f16.f16 " \
        "{%0,%1},{%2,%3,%4,%5},{%6,%7},{%8,%9};" \
        : "=r"(d0), "=r"(d1) \
        : "r"(a0), "r"(a1), "r"(a2), "r"(a3), "r"(b0), "r"(b1), "r"(c0), "r"(c1))

#define HMAX2(d, a, b) \
    asm("max.f16x2 %0, %1, %2;" : "=r"(d) : "r"(a), "r"(b))

__device__ __forceinline__ void cp16(uint32_t dst, const void* src) {
    asm volatile("cp.async.cg.shared.global [%0], [%1], 16;" :: "r"(dst), "l"(src));
}
#define CP_COMMIT() asm volatile("cp.async.commit_group;" ::: "memory")
#define CP_WAIT(n)  asm volatile("cp.async.wait_group %0;" :: "n"(n) : "memory")

// ---------------- prep: 4 threads per row (quad shfl-reduce) ----------------
__global__ void kde_prep(const float* __restrict__ xe, const float* __restrict__ xb) {
    int gt = blockIdx.x * blockDim.x + threadIdx.x;      // 0..131071
    int g = gt >> 2;                                     // row id 0..32767
    int q = gt & 3;                                      // quarter within row
    bool is_e = g < N_PTS;
    int row = is_e ? g : g - N_PTS;
    const float* src = (is_e ? xe : xb) + (size_t)row * D;

    float4 t = ((const float4*)src)[q];
    float n2 = t.x*t.x + t.y*t.y + t.z*t.z + t.w*t.w;
    n2 += __shfl_xor_sync(0xffffffffu, n2, 1);
    n2 += __shfl_xor_sync(0xffffffffu, n2, 2);           // full ||x||^2 in all 4 lanes

    float sc = is_e ? 100.f : 1.f;
    __half r[4];
    r[0] = __float2half(sc * t.x);
    r[1] = __float2half(sc * t.y);
    r[2] = __float2half(sc * t.z);
    r[3] = __float2half(sc * t.w);

    if (q == 0) {
        if (is_e) g_ce[row] = T1_CONST - 50.f * n2;
        else      g_cbh[row] = __float2half(-50.f * n2);
    }
    uint2* dst = (uint2*)((is_e ? g_A : g_B) + (size_t)row * ROWB + q * 8);
    *dst = *(const uint2*)r;
}

// ---------------- main: f16 HMMA GEMM, warp owns m64 (4 m16 tiles) -----------------
// grid = 1024: blockIdx.x = mblk*16 + split. CTA = 128 thr (4 warps), CTA covers m256.
// B fragments + cb loads amortized over 2x HMMAs vs m32/warp. 3-stage cp.async ring.
__global__ void __launch_bounds__(128) kde_main() {
    __shared__ __align__(16) unsigned char sA[MB_ROWS * SROWB];
    __shared__ __align__(16) unsigned char sB[NSTAGE][BT * SROWB];
    __shared__ __align__(16) __half scb[NSTAGE][BT];

    const int tid = threadIdx.x, w = tid >> 5, lane = tid & 31;
    const int mblk = blockIdx.x >> 4, split = blockIdx.x & 15;

    const unsigned char* Ag = g_A + (size_t)mblk * MB_ROWS * ROWB;
    const unsigned char* Bg = g_B + (size_t)split * (N_PTS / NSPLITS) * ROWB;
    const __half* cbg = g_cbh + (size_t)split * (N_PTS / NSPLITS);

    const uint32_t sA_a = smem_u32(sA);
    uint32_t sB_a[NSTAGE], scb_a[NSTAGE];
    #pragma unroll
    for (int s = 0; s < NSTAGE; s++) { sB_a[s] = smem_u32(sB[s]); scb_a[s] = smem_u32(scb[s]); }

    // copy helper: B tile -> stage buffer (32B rows -> 48B smem stride), 2 cp16/thread
    auto issue_tile = [&](int t, int s) {
        const unsigned char* src = Bg + (size_t)t * BT * ROWB;
        #pragma unroll
        for (int k = 0; k < 2; k++) {
            int i = tid + k * 128;            // 256 chunks of 16B
            uint32_t row = i >> 1, c = i & 1;
            cp16(sB_a[s] + row * SROWB + c * 16, src + (size_t)i * 16);
        }
        if (tid < 16) cp16(scb_a[s] + tid * 16, cbg + (size_t)t * BT + tid * 8);
    };

    // Prologue: group0 = A + tile0, group1 = tile1.
    {
        #pragma unroll
        for (int k = 0; k < 4; k++) {
            int i = tid + k * 128;            // 512 chunks of 16B (256 rows)
            uint32_t row = i >> 1, c = i & 1;
            cp16(sA_a + row * SROWB + c * 16, Ag + (size_t)i * 16);
        }
        issue_tile(0, 0);
        CP_COMMIT();
        issue_tile(1, 1);
        CP_COMMIT();
        CP_WAIT(1);              // group0 (A + tile0) complete
    }
    __syncthreads();

    // A fragments (4 m16-tiles = m64 per warp, K=16), loaded once per warp.
    uint32_t af[4][4];
    {
        int grp = lane >> 3;
        int arow = ((grp & 1) << 3) + (lane & 7);      // 0..15 within m16 tile
        int akb  = (grp >> 1) << 4;                    // 0 or 16 bytes
        #pragma unroll
        for (int mt = 0; mt < 4; mt++) {
            uint32_t addr = sA_a + (uint32_t)(w * 64 + mt * 16 + arow) * SROWB + (uint32_t)akb;
            LDMX4(af[mt][0], af[mt][1], af[mt][2], af[mt][3], addr);
        }
    }

    // B ldmatrix: one x4 covers 16 cols x K16 ({b0,b1}=cols 0-7, {b2,b3}=cols 8-15).
    const uint32_t boff = ((uint32_t)(((lane >> 4) << 3) + (lane & 7))) * SROWB
                        + (uint32_t)(((lane >> 3) & 1) << 4);
    const uint32_t cb_off = (uint32_t)((lane & 3) << 2);   // byte offset of packed half2 (cols 2q,2q+1)
    const uint32_t NEG_INF2 = 0xFC00FC00u;                 // (-inf, -inf) f16x2
    uint32_t rm[8];
    #pragma unroll
    for (int i = 0; i < 8; i++) rm[i] = NEG_INF2;

    for (int t = 0; t < TILES_PER_SPLIT; t++) {
        const int cur = t % NSTAGE;

        if (t + 1 < TILES_PER_SPLIT) { CP_WAIT(1); } else { CP_WAIT(0); }
        __syncthreads();   // tile t ready everywhere; buf (t+2)%3 free (all done with t-1)

        const uint32_t bbase = sB_a[cur] + boff;
        const uint32_t cbase = scb_a[cur] + cb_off;
        #pragma unroll
        for (int n16 = 0; n16 < 8; n16++) {
            uint32_t b0, b1, b2, b3;
            LDMX4(b0, b1, b2, b3, bbase + (uint32_t)n16 * (16 * SROWB));
            uint32_t cA, cB;     // packed (cb_c, cb_c+1) for this thread's col pair
            asm volatile("ld.shared.b32 %0, [%1];" : "=r"(cA) : "r"(cbase + n16 * 32));
            asm volatile("ld.shared.b32 %0, [%1];" : "=r"(cB) : "r"(cbase + n16 * 32 + 16));
            #pragma unroll
            for (int mt = 0; mt < 4; mt++) {
                uint32_t d0, d1, e0, e1;
                MMA16816H(d0, d1, af[mt][0], af[mt][1], af[mt][2], af[mt][3], b0, b1, cA, cA);
                MMA16816H(e0, e1, af[mt][0], af[mt][1], af[mt][2], af[mt][3], b2, b3, cB, cB);
                uint32_t t0, t1;
                HMAX2(t0, d0, e0);                    // row r
                HMAX2(rm[mt * 2 + 0], rm[mt * 2 + 0], t0);
                HMAX2(t1, d1, e1);                    // row r+8
                HMAX2(rm[mt * 2 + 1], rm[mt * 2 + 1], t1);
            }
        }

        if (t + 2 < TILES_PER_SPLIT) {
            issue_tile(t + 2, (t + 2) % NSTAGE);
            CP_COMMIT();
        }
    }

    // reduce across the 4-lane quad (cols), then unpack and store per-row maxes
    #pragma unroll
    for (int i = 0; i < 8; i++) {
        uint32_t o;
        o = __shfl_xor_sync(0xffffffffu, rm[i], 1); HMAX2(rm[i], rm[i], o);
        o = __shfl_xor_sync(0xffffffffu, rm[i], 2); HMAX2(rm[i], rm[i], o);
    }
    if ((lane & 3) == 0) {
        int q = lane >> 2;
        int base = mblk * MB_ROWS + w * 64;
        #pragma unroll
        for (int mt = 0; mt < 4; mt++) {
            #pragma unroll
            for (int h = 0; h < 2; h++) {
                __half2 v = *(__half2*)&rm[mt * 2 + h];
                float m = fmaxf(__half2float(__low2half(v)), __half2float(__high2half(v)));
                g_rowmax[split][base + mt * 16 + h * 8 + q] = m;
            }
        }
    }
}

// ---------------- final: exact recompute for flagged rows, const for the rest ----
__global__ void kde_final(const float* __restrict__ xe, const float* __restrict__ xb,
                          float* __restrict__ out) {
    __shared__ int s_list[128];
    __shared__ int s_cnt;
    __shared__ float s_red[128];
    __shared__ float s_e[D];

    int tid = threadIdx.x;
    int row = blockIdx.x * 128 + tid;
    if (tid == 0) s_cnt = 0;
    __syncthreads();

    float mv = -3.0e38f;
    #pragma unroll
    for (int k = 0; k < NSPLITS; k++) mv = fmaxf(mv, g_rowmax[k][row]);
    mv += g_ce[row];
    if (mv > FLAG_THRESH) {
        int p = atomicAdd(&s_cnt, 1);
        s_list[p] = row;
    } else {
        out[row] = LOG_EPS;
    }
    __syncthreads();

    for (int f = 0; f < s_cnt; f++) {
        int i = s_list[f];
        if (tid < D) s_e[tid] = xe[(size_t)i * D + tid];
        __syncthreads();
        float e[D];
        #pragma unroll
        for (int k = 0; k < D; k++) e[k] = s_e[k];
        float acc = 0.f;
        for (int j = tid; j < N_PTS; j += 128) {
            const float4* bp = (const float4*)(xb + (size_t)j * D);
            float sq = 0.f;
            #pragma unroll
            for (int q = 0; q < 4; q++) {
                float4 b = bp[q];
                float d0 = e[4*q+0] - b.x, d1 = e[4*q+1] - b.y;
                float d2 = e[4*q+2] - b.z, d3 = e[4*q+3] - b.w;
                sq += d0*d0 + d1*d1 + d2*d2 + d3*d3;
            }
            float s = T1_CONST - 50.f * sq;
            if (s > -87.0f) acc += __expf(s);
        }
        s_red[tid] = acc;
        __syncthreads();
        for (int st = 64; st > 0; st >>= 1) {
            if (tid < st) s_red[tid] += s_red[tid + st];
            __syncthreads();
        }
        if (tid == 0) out[i] = logf(1e-8f + s_red[0] * (1.0f / (float)N_PTS));
        __syncthreads();
    }
}

extern "C" void kernel_launch(void* const* d_in, const int* in_sizes, int n_in,
                              void* d_out, int out_size) {
    const float* x_eval = (const float*)d_in[0];
    const float* x_base = (const float*)d_in[1];
    float* out = (float*)d_out;

    kde_prep<<<(2 * N_PTS * 4) / 256, 256>>>(x_eval, x_base);
    kde_main<<<(N_PTS / MB_ROWS) * NSPLITS, 128>>>();
    kde_final<<<N_PTS / 128, 128>>>(x_eval, x_base, out);
}